// round 7
// baseline (speedup 1.0000x reference)
#include <cuda_runtime.h>

#define NPTS    8192
#define BATCH   4
#define NPOINT  2048
#define NSAMPLE 32
#define CIN     67
#define COUT    128
#define KTOT    (CIN * NSAMPLE)   // 2144
#define R2      0.04f

#define TPB     512
#define PPT     (NPTS / TPB)      // 16 points per thread (FPS)
#define NPAIR   (PPT / 2)         // 8 packed pairs

#define WPB     35                // worker CTAs per batch
#define NWORK   (WPB * BATCH)     // 140 workers
#define TILE    16                // centers per steady-state conv tile
#define TILES16 120               // 16-center tiles per batch (centers 0..1920)
#define MINI_BASE 1920            // final 128 centers -> 32 minitiles of 4
#define NMINI   32
#define WPAD    132               // s_w row pitch (132 % 32 == 4 -> conflict-free)

typedef unsigned long long ull;

// progress flags: one 128B line per batch (no cross-batch L2-line contention)
__device__ int g_progress[BATCH * 32];

// ---------------------------------------------------------------------------
// packed f32x2 helpers (sm_103a) — add/sub/mul only
// ---------------------------------------------------------------------------
__device__ __forceinline__ ull f2pk(float lo, float hi) {
    ull r; asm("mov.b64 %0, {%1, %2};" : "=l"(r) : "f"(lo), "f"(hi)); return r;
}
__device__ __forceinline__ void f2unpk(ull v, float& lo, float& hi) {
    asm("mov.b64 {%0, %1}, %2;" : "=f"(lo), "=f"(hi) : "l"(v));
}
__device__ __forceinline__ ull f2add(ull a, ull b) {
    ull r; asm("add.rn.f32x2 %0, %1, %2;" : "=l"(r) : "l"(a), "l"(b)); return r;
}
__device__ __forceinline__ ull f2sub(ull a, ull b) {
    ull r; asm("sub.rn.f32x2 %0, %1, %2;" : "=l"(r) : "l"(a), "l"(b)); return r;
}
__device__ __forceinline__ ull f2mul(ull a, ull b) {
    ull r; asm("mul.rn.f32x2 %0, %1, %2;" : "=l"(r) : "l"(a), "l"(b)); return r;
}

__global__ void reset_kernel() {
    if (threadIdx.x < BATCH * 32) g_progress[threadIdx.x] = 0;
}

// ---------------------------------------------------------------------------
// worker helpers
// ---------------------------------------------------------------------------
__device__ __forceinline__ void wait_progress(const int* flag, int target) {
    if (threadIdx.x == 0) {
        unsigned pr;
        while (true) {
            asm volatile("ld.acquire.gpu.global.u32 %0, [%1];"
                         : "=r"(pr) : "l"(flag) : "memory");
            if ((int)pr >= target) break;
            __nanosleep(256);
        }
    }
    __syncthreads();
}

// one warp collects the ball-query row for one center into smem
__device__ __forceinline__ void ball_one(const float* __restrict__ P,
                                         const float* __restrict__ nx,
                                         size_t crow, int lane,
                                         int* row, float* ctr3)
{
    const float cx = nx[crow + 0];
    const float cy = nx[crow + 1];
    const float cz = nx[crow + 2];
    if (lane < 3) ctr3[lane] = nx[crow + lane];

    int filled = 0, first = 0;
    for (int basei = 0; basei < NPTS; basei += 32) {
        const int i = basei + lane;
        float dx = __fadd_rn(P[i * 3 + 0], -cx);
        float dy = __fadd_rn(P[i * 3 + 1], -cy);
        float dz = __fadd_rn(P[i * 3 + 2], -cz);
        float d2 = __fadd_rn(__fadd_rn(__fmul_rn(dx, dx), __fmul_rn(dy, dy)),
                             __fmul_rn(dz, dz));
        unsigned m = __ballot_sync(0xffffffffu, d2 < R2);
        if (filled == 0 && m) first = basei + __ffs(m) - 1;
        if (d2 < R2) {
            int pos = filled + __popc(m & ((1u << lane) - 1));
            if (pos < NSAMPLE) row[pos] = i;
        }
        filled += __popc(m);
        if (filled >= NSAMPLE) break;
    }
    for (int j = filled + lane; j < NSAMPLE; j += 32) row[j] = first;
}

// ---------------------------------------------------------------------------
// Fused persistent kernel.
// Blocks 0..3: FPS. Blocks 4..143: workers (16-center tiles RR, then one
// 4-center minitile each for the final 128 centers -> short post-FPS tail).
// ---------------------------------------------------------------------------
__global__ void __launch_bounds__(TPB, 1)
fused_kernel(const float* __restrict__ points,
             const float* __restrict__ features,
             const float* __restrict__ weight,
             float* __restrict__ new_xyz,
             float* __restrict__ conv_out)
{
    extern __shared__ char smraw[];
    __shared__ ull redw[2][TPB / 32];

    const int t = threadIdx.x;
    const int lane = t & 31;
    const int w = t >> 5;

    if (blockIdx.x < BATCH) {
        // ======================= FPS role =======================
        const int b = blockIdx.x;
        float4* pts4 = (float4*)smraw;           // NPTS float4 = 128 KB
        const float* P = points + (size_t)b * NPTS * 3;

        for (int i = t; i < NPTS; i += TPB)
            pts4[i] = make_float4(P[3 * i], P[3 * i + 1], P[3 * i + 2], 0.0f);
        __syncthreads();

        const int base = t * PPT;
        ull px2[NPAIR], py2[NPAIR], pz2[NPAIR];
        float dist[PPT];
#pragma unroll
        for (int j = 0; j < NPAIR; j++) {
            float4 a = pts4[base + 2 * j];
            float4 c = pts4[base + 2 * j + 1];
            px2[j] = f2pk(a.x, c.x);
            py2[j] = f2pk(a.y, c.y);
            pz2[j] = f2pk(a.z, c.z);
        }
#pragma unroll
        for (int j = 0; j < PPT; j++) dist[j] = 1e10f;

        float4 q0 = pts4[0];
        float lx = q0.x, ly = q0.y, lz = q0.z;
        if (t == 0) {
            float* o = new_xyz + (size_t)b * NPOINT * 3;
            o[0] = lx; o[1] = ly; o[2] = lz;
        }

        for (int iter = 1; iter < NPOINT; ++iter) {
            const int par = iter & 1;
            const ull lxp = f2pk(lx, lx);
            const ull lyp = f2pk(ly, ly);
            const ull lzp = f2pk(lz, lz);

            float bv = -1.0f;
#pragma unroll
            for (int j = 0; j < NPAIR; j++) {
                // identical arithmetic to reference: (dx*dx+dy*dy)+dz*dz, rn
                ull dx = f2sub(px2[j], lxp);
                ull dy = f2sub(py2[j], lyp);
                ull dz = f2sub(pz2[j], lzp);
                ull d2 = f2add(f2add(f2mul(dx, dx), f2mul(dy, dy)), f2mul(dz, dz));
                float d0, d1;
                f2unpk(d2, d0, d1);
                float n0 = fminf(dist[2 * j + 0], d0);
                float n1 = fminf(dist[2 * j + 1], d1);
                dist[2 * j + 0] = n0;
                dist[2 * j + 1] = n1;
                bv = fmaxf(bv, fmaxf(n0, n1));
            }

            // warp max (dist >= 0 -> uint order == float order)
            const unsigned bb = __float_as_uint(bv);
            const unsigned wm = __reduce_max_sync(0xffffffffu, bb);

            // winner-only rescan (predicated off for non-winning threads)
            unsigned li = 0x7fffffffu;
            if (bb == wm) {
#pragma unroll
                for (int j = PPT - 1; j >= 0; j--)
                    if (__float_as_uint(dist[j]) == wm) li = base + j;
            }
            const unsigned wi_ = __reduce_min_sync(0xffffffffu, li);
            if (lane == 0)
                redw[par][w] = ((ull)wm << 32) | wi_;
            __syncthreads();                               // the ONLY barrier

            // every warp reduces the 16 warp results
            const ull v = (lane < TPB / 32) ? redw[par][lane] : 0ull;
            const unsigned hv = (unsigned)(v >> 32);
            const unsigned lv = (unsigned)v;
            const unsigned gmv = __reduce_max_sync(0xffffffffu, hv);
            const unsigned ii = (hv == gmv) ? lv : 0x7fffffffu;
            const int best = (int)__reduce_min_sync(0xffffffffu, ii);

            float4 q = pts4[best];
            lx = q.x; ly = q.y; lz = q.z;
            if (t == 0) {
                float* o = new_xyz + ((size_t)b * NPOINT + iter) * 3;
                o[0] = lx; o[1] = ly; o[2] = lz;
                if ((iter & 31) == 31)
                    asm volatile("st.release.gpu.global.u32 [%0], %1;"
                                 :: "l"(g_progress + b * 32), "r"(iter + 1) : "memory");
            }
        }
    } else {
        // ======================= worker role =======================
        const int wi = blockIdx.x - BATCH;       // 0..NWORK-1
        const int b = wi / WPB;
        const int wslot = wi - b * WPB;

        float* s_g   = (float*)smraw;                   // [16][128]
        float* s_w   = s_g + TILE * 128;                // [128][WPAD]
        int*   s_idx = (int*)(s_w + COUT * WPAD);       // [16][32]
        float* s_ctr = (float*)(s_idx + TILE * NSAMPLE);// [16][3]

        const float*  P  = points + (size_t)b * NPTS * 3;
        const float4* F4 = (const float4*)(features + (size_t)b * NPTS * 64);
        const int* flag = g_progress + b * 32;

        // ---------- steady state: 16-center tiles, round-robin ----------
        for (int tile = wslot; tile < TILES16; tile += WPB) {
            const int p0 = tile * TILE;
            wait_progress(flag, p0 + TILE);

            // ball query: warp w handles center p0+w
            ball_one(P, new_xyz, ((size_t)b * NPOINT + p0 + w) * 3, lane,
                     s_idx + w * NSAMPLE, s_ctr + w * 3);
            __syncthreads();

            const int og = lane;
            const int pg = w;
            const int myidx = s_idx[pg * NSAMPLE + lane];

            float acc[4] = {0.0f, 0.0f, 0.0f, 0.0f};
            for (int chunk = 0; chunk < 17; chunk++) {
                const int c0   = (chunk == 0) ? 0 : (4 * chunk - 1);
                const int kend = (chunk == 0) ? 96 : 128;
                __syncthreads();

                if (chunk == 0) {
#pragma unroll
                    for (int ci = 0; ci < 3; ci++)
                        s_g[pg * 128 + ci * 32 + lane] =
                            P[myidx * 3 + ci] - s_ctr[pg * 3 + ci];
                } else {
                    float4 fv = F4[(size_t)myidx * 16 + (chunk - 1)];
                    s_g[pg * 128 +  0 + lane] = fv.x;
                    s_g[pg * 128 + 32 + lane] = fv.y;
                    s_g[pg * 128 + 64 + lane] = fv.z;
                    s_g[pg * 128 + 96 + lane] = fv.w;
                }
#pragma unroll
                for (int q = 0; q < 8; q++) {
                    const int task = q * TPB + t;
                    const int o = task >> 5;
                    const int k4 = (task & 31) * 4;
                    if (k4 < kend)
                        *(float4*)&s_w[o * WPAD + k4] =
                            *(const float4*)(weight + (size_t)o * KTOT + c0 * 32 + k4);
                }
                __syncthreads();

                for (int kk = 0; kk < kend; kk += 4) {
                    float4 w0 = *(const float4*)&s_w[(og +  0) * WPAD + kk];
                    float4 w1 = *(const float4*)&s_w[(og + 32) * WPAD + kk];
                    float4 w2 = *(const float4*)&s_w[(og + 64) * WPAD + kk];
                    float4 w3 = *(const float4*)&s_w[(og + 96) * WPAD + kk];
                    float4 g  = *(const float4*)&s_g[pg * 128 + kk];
                    acc[0] = fmaf(g.x, w0.x, fmaf(g.y, w0.y, fmaf(g.z, w0.z, fmaf(g.w, w0.w, acc[0]))));
                    acc[1] = fmaf(g.x, w1.x, fmaf(g.y, w1.y, fmaf(g.z, w1.z, fmaf(g.w, w1.w, acc[1]))));
                    acc[2] = fmaf(g.x, w2.x, fmaf(g.y, w2.y, fmaf(g.z, w2.z, fmaf(g.w, w2.w, acc[2]))));
                    acc[3] = fmaf(g.x, w3.x, fmaf(g.y, w3.y, fmaf(g.z, w3.z, fmaf(g.w, w3.w, acc[3]))));
                }
            }

            float* dst = conv_out + ((size_t)b * NPOINT + p0 + pg) * COUT;
            dst[og +  0] = acc[0];
            dst[og + 32] = acc[1];
            dst[og + 64] = acc[2];
            dst[og + 96] = acc[3];
            __syncthreads();
        }

        // ---------- tail: one 4-center minitile per worker ----------
        if (wslot < NMINI) {
            const int p0 = MINI_BASE + wslot * 4;
            wait_progress(flag, p0 + 4);

            if (w < 4)
                ball_one(P, new_xyz, ((size_t)b * NPOINT + p0 + w) * 3, lane,
                         s_idx + w * NSAMPLE, s_ctr + w * 3);
            __syncthreads();

            const int o = t & 127;          // one output per thread
            const int p = t >> 7;           // one point per thread
            const int myidx = (t < 128) ? s_idx[(t >> 5) * NSAMPLE + lane] : 0;

            float acc = 0.0f;
            for (int chunk = 0; chunk < 17; chunk++) {
                const int c0   = (chunk == 0) ? 0 : (4 * chunk - 1);
                const int kend = (chunk == 0) ? 96 : 128;
                __syncthreads();

                if (t < 128) {              // 4 points x 32 samples
                    const int pp = t >> 5;
                    if (chunk == 0) {
#pragma unroll
                        for (int ci = 0; ci < 3; ci++)
                            s_g[pp * 128 + ci * 32 + lane] =
                                P[myidx * 3 + ci] - s_ctr[pp * 3 + ci];
                    } else {
                        float4 fv = F4[(size_t)myidx * 16 + (chunk - 1)];
                        s_g[pp * 128 +  0 + lane] = fv.x;
                        s_g[pp * 128 + 32 + lane] = fv.y;
                        s_g[pp * 128 + 64 + lane] = fv.z;
                        s_g[pp * 128 + 96 + lane] = fv.w;
                    }
                }
#pragma unroll
                for (int q = 0; q < 8; q++) {
                    const int task = q * TPB + t;
                    const int oo = task >> 5;
                    const int k4 = (task & 31) * 4;
                    if (k4 < kend)
                        *(float4*)&s_w[oo * WPAD + k4] =
                            *(const float4*)(weight + (size_t)oo * KTOT + c0 * 32 + k4);
                }
                __syncthreads();

                for (int kk = 0; kk < kend; kk += 4) {
                    float4 wv = *(const float4*)&s_w[o * WPAD + kk];
                    float4 g  = *(const float4*)&s_g[p * 128 + kk];
                    acc = fmaf(g.x, wv.x, fmaf(g.y, wv.y, fmaf(g.z, wv.z, fmaf(g.w, wv.w, acc))));
                }
            }
            conv_out[((size_t)b * NPOINT + p0 + p) * COUT + o] = acc;
        }
    }
}

// ---------------------------------------------------------------------------

extern "C" void kernel_launch(void* const* d_in, const int* in_sizes, int n_in,
                              void* d_out, int out_size)
{
    const float* points   = (const float*)d_in[0];
    const float* features = (const float*)d_in[1];
    const float* weight   = (const float*)d_in[2];
    float* out = (float*)d_out;
    float* new_xyz = out;                            // B*NPOINT*3
    float* conv    = out + BATCH * NPOINT * 3;       // B*NPOINT*COUT

    const int smem = NPTS * sizeof(float4);          // 128 KB (worker fits too)
    cudaFuncSetAttribute(fused_kernel, cudaFuncAttributeMaxDynamicSharedMemorySize, smem);

    reset_kernel<<<1, 128>>>();
    fused_kernel<<<BATCH + NWORK, TPB, smem>>>(points, features, weight, new_xyz, conv);
}